// round 15
// baseline (speedup 1.0000x reference)
#include <cuda_runtime.h>
#include <cooperative_groups.h>
#include <math.h>

namespace cg = cooperative_groups;

#define NFFT   32768
#define BATCH  8
#define TPB1   512       // threads per cluster-8 FFT CTA
#define TPB2   256       // threads per cluster-16 FFT CTA

#define TWO_PI 6.283185307179586476925f
#define SCALE  1.6858739404357614e-07f   // 1 / 32768^1.5

// ---------------- scratch (static device globals; no allocation) -------------
__device__ float  g_S[BATCH * 16 * 512];       // RAW exp [b][f][k] (transposed)
__device__ float  g_part[BATCH * 16 * 16];     // partial sums [b][f][slice]
__device__ float2 g_bufA[BATCH * NFFT];

__device__ __forceinline__ float2 cmul(float2 a, float2 b) {
  return make_float2(a.x*b.x - a.y*b.y, a.x*b.y + a.y*b.x);
}

#define PADI(i) ((i) + ((i) >> 3))
#define SMSZ8   (4096 + 512)     // cluster-8 buffers (4096-pt)
#define SMSZ16  (2048 + 256)     // cluster-16 buffers (2048-pt)
#define CBSZ    (16 * 128)       // mirror-exchange buffer [k2][t]

// ---------------- small DFT kernels (registers) -------------------------------
__device__ __forceinline__ void fft8(float2 v[8]) {
  const float S = 0.70710678118654752440f;
  float2 t;
  t = v[1]; v[1] = v[4]; v[4] = t;      // bit-reverse
  t = v[3]; v[3] = v[6]; v[6] = t;
#define BF(a,b)  { t = v[b]; v[b] = make_float2(v[a].x - t.x, v[a].y - t.y); \
                   v[a] = make_float2(v[a].x + t.x, v[a].y + t.y); }
#define BFMI(a,b){ t = make_float2(v[b].y, -v[b].x); \
                   v[b] = make_float2(v[a].x - t.x, v[a].y - t.y); \
                   v[a] = make_float2(v[a].x + t.x, v[a].y + t.y); }
  BF(0,1) BF(2,3) BF(4,5) BF(6,7)
  BF(0,2) BFMI(1,3) BF(4,6) BFMI(5,7)
  BF(0,4)
  { float2 w = make_float2(S, -S);  t = cmul(w, v[5]);
    v[5] = make_float2(v[1].x - t.x, v[1].y - t.y);
    v[1] = make_float2(v[1].x + t.x, v[1].y + t.y); }
  BFMI(2,6)
  { float2 w = make_float2(-S, -S); t = cmul(w, v[7]);
    v[7] = make_float2(v[3].x - t.x, v[3].y - t.y);
    v[3] = make_float2(v[3].x + t.x, v[3].y + t.y); }
#undef BF
#undef BFMI
}

__device__ __forceinline__ void fft4(float2 v[4]) {
  float2 t;
  t = v[1]; v[1] = v[2]; v[2] = t;      // bit-reverse
  t = v[1]; v[1] = make_float2(v[0].x - t.x, v[0].y - t.y);
            v[0] = make_float2(v[0].x + t.x, v[0].y + t.y);
  t = v[3]; v[3] = make_float2(v[2].x - t.x, v[2].y - t.y);
            v[2] = make_float2(v[2].x + t.x, v[2].y + t.y);
  t = v[2]; v[2] = make_float2(v[0].x - t.x, v[0].y - t.y);
            v[0] = make_float2(v[0].x + t.x, v[0].y + t.y);
  t = make_float2(v[3].y, -v[3].x);
            v[3] = make_float2(v[1].x - t.x, v[1].y - t.y);
            v[1] = make_float2(v[1].x + t.x, v[1].y + t.y);
}

__device__ __forceinline__ void fft16(float2 v[16]) {
  float2 E[8], O[8];
#pragma unroll
  for (int i = 0; i < 8; i++) { E[i] = v[2*i]; O[i] = v[2*i+1]; }
  fft8(E); fft8(O);
  const float2 W16[8] = {
    { 1.0f, 0.0f},
    { 0.9238795325112867f, -0.3826834323650898f},
    { 0.7071067811865476f, -0.7071067811865476f},
    { 0.3826834323650898f, -0.9238795325112867f},
    { 0.0f, -1.0f},
    {-0.3826834323650898f, -0.9238795325112867f},
    {-0.7071067811865476f, -0.7071067811865476f},
    {-0.9238795325112867f, -0.3826834323650898f},
  };
#pragma unroll
  for (int k = 0; k < 8; k++) {
    float2 t = cmul(W16[k], O[k]);
    v[k]     = make_float2(E[k].x + t.x, E[k].y + t.y);
    v[k + 8] = make_float2(E[k].x - t.x, E[k].y - t.y);
  }
}

// v[r] *= exp(i*ang*r): one sincos + chained complex muls (MUFU-cheap)
__device__ __forceinline__ void twiddle_ramp(float2 v[8], float ang) {
  float s, c; __sincosf(ang, &s, &c);
  const float2 st = make_float2(c, s);
  float2 w = st;
  v[1] = cmul(v[1], w);
#pragma unroll
  for (int r = 2; r < 8; r++) { w = cmul(w, st); v[r] = cmul(v[r], w); }
}
__device__ __forceinline__ void twiddle_ramp4(float2 v[4], float ang) {
  float s, c; __sincosf(ang, &s, &c);
  const float2 st = make_float2(c, s);
  float2 w = st;
  v[1] = cmul(v[1], w); w = cmul(w, st);
  v[2] = cmul(v[2], w); w = cmul(w, st);
  v[3] = cmul(v[3], w);
}

// radix-8 Stockham smem stage, stride = TPB (total = 8*TPB points)
__device__ __forceinline__ void smem_stage(float2* sm, float2 v[8], int j, int NS, int TPB) {
#pragma unroll
  for (int r = 0; r < 8; r++) v[r] = sm[PADI(j + r * TPB)];
  __syncthreads();
  const int m = j & (NS - 1);
  twiddle_ramp(v, -(TWO_PI / (8.0f * NS)) * (float)m);
  fft8(v);
  const int base = (j / NS) * (NS * 8) + m;
#pragma unroll
  for (int r = 0; r < 8; r++) sm[PADI(base + r * NS)] = v[r];
  __syncthreads();
}

// ---------------- kernel 1: softmax (raw exps + partial sums) ----------------
__global__ void __launch_bounds__(512) k_softmax(const float* __restrict__ ds) {
  const int b    = blockIdx.x;
  const int tid  = threadIdx.x;
  const int w    = tid >> 5, lane = tid & 31;
  const int q    = w & 3;
  const int kgrp = w >> 2;
  const int k    = blockIdx.y * 128 + kgrp * 32 + lane;

  const float4 x = *(const float4*)(ds + (size_t)b * 8192 + (size_t)k * 16 + q * 4);
  float e0 = __expf(x.x), e1 = __expf(x.y), e2 = __expf(x.z), e3 = __expf(x.w);

  float* Sb = g_S + b * 8192;
  Sb[(q * 4 + 0) * 512 + k] = e0;
  Sb[(q * 4 + 1) * 512 + k] = e1;
  Sb[(q * 4 + 2) * 512 + k] = e2;
  Sb[(q * 4 + 3) * 512 + k] = e3;

  float s0 = e0, s1 = e1, s2 = e2, s3 = e3;
#pragma unroll
  for (int o = 16; o > 0; o >>= 1) {
    s0 += __shfl_xor_sync(0xffffffff, s0, o);
    s1 += __shfl_xor_sync(0xffffffff, s1, o);
    s2 += __shfl_xor_sync(0xffffffff, s2, o);
    s3 += __shfl_xor_sync(0xffffffff, s3, o);
  }
  if (lane == 0) {
    const int slice = blockIdx.y * 4 + kgrp;
    g_part[(b * 16 + q * 4 + 0) * 16 + slice] = s0;
    g_part[(b * 16 + q * 4 + 1) * 16 + slice] = s1;
    g_part[(b * 16 + q * 4 + 2) * 16 + slice] = s2;
    g_part[(b * 16 + q * 4 + 3) * 16 + slice] = s3;
  }
}

// ---------------- kernel 2: comb divisor-sum + impulse + pack ----------------
// 16 sub-threads per sample (j ≡ sub mod 16), hoisted isqrt loop bound.
// Block = 1024 threads = 64 samples; frame S-table staged in smem once.
__global__ void __launch_bounds__(1024) k_build(const float* __restrict__ impulse,
                                                const float* __restrict__ damping,
                                                const float* __restrict__ noise,
                                                int cmask, int csh, int n1len) {
  __shared__ float Sf[4096];
  __shared__ float partsm[128];
  __shared__ float binv_sm[8];
  __shared__ float rcp_s[184];
  const int tid = threadIdx.x;
  const int n0  = blockIdx.x * 64;
  const int fr  = n0 >> 11;

  if (tid >= 1 && tid < 184) rcp_s[tid] = 1.0f / (float)tid;
  if (tid < 128) {
    const int b = tid >> 4, sl = tid & 15;
    partsm[tid] = g_part[(b * 16 + fr) * 16 + sl];
  }
#pragma unroll
  for (int i = 0; i < 4; i++) {
    const int idx = tid + i * 1024;
    Sf[idx] = g_S[(idx >> 9) * 8192 + fr * 512 + (idx & 511)];
  }
  __syncthreads();
  if (tid < 8) {
    float s = 0.0f;
#pragma unroll
    for (int sl = 0; sl < 16; sl++) s += partsm[tid * 16 + sl];
    binv_sm[tid] = 1.0f / s;
  }
  __syncthreads();

  const int n   = n0 + (tid >> 4);     // 64 samples per block
  const int sub = tid & 15;            // 16-way divisor-scan split

  float dsum[BATCH];
#pragma unroll
  for (int b = 0; b < BATCH; b++) dsum[b] = 0.0f;

  {
    // hoisted integer sqrt bound (exact for n < 2^15)
    int limit = (int)sqrtf((float)n);
    if ((limit + 1) * (limit + 1) <= n) limit++;
    if (limit * limit > n) limit--;

    const float nf = (float)n + 0.5f;
    for (int j = sub + 1; j <= limit; j += 16) {
      const int q = (int)(nf * rcp_s[j]);
      if (q * j == n) {
#pragma unroll
        for (int b = 0; b < BATCH; b++) dsum[b] += Sf[b * 512 + (j - 1)];
        if (q != j && q <= 512) {
#pragma unroll
          for (int b = 0; b < BATCH; b++) dsum[b] += Sf[b * 512 + (q - 1)];
        }
      }
    }
  }

  // butterfly combine over the 16 sub-threads (lanes differing in low 4 bits)
#pragma unroll
  for (int m = 1; m < 16; m <<= 1) {
#pragma unroll
    for (int b = 0; b < BATCH; b++)
      dsum[b] += __shfl_xor_sync(0xffffffff, dsum[b], m);
  }

  // lanes sub < 8 write batch b = sub
  if (sub < 8) {
    const int b = sub;
    float pos = (n + 0.5f) * (1.0f / 256.0f) - 0.5f;
    pos = fminf(fmaxf(pos, 0.0f), 127.0f);
    const int i0 = (int)pos;
    const int i1 = min(i0 + 1, 127);
    const float wgt = pos - (float)i0;
    float a0 = impulse[b * 128 + i0]; a0 *= a0;
    float a1 = impulse[b * 128 + i1]; a1 *= a1;
    const float impv = (a0 * (1.0f - wgt) + a1 * wgt) * noise[b * NFFT + n];
    const float dmp  = 0.9999f / (1.0f + expf(-damping[b]));
    const float dval = (n == 0) ? 1.0f : dsum[b] * binv_sm[b];
    const int pidx = (n & cmask) * n1len + (n >> csh);
    g_bufA[b * NFFT + pidx] = make_float2(dmp * dval, impv);
  }
}

// ---------------- spectrum helpers -------------------------------------------
__device__ __forceinline__ float fenv_of(const float* __restrict__ sigf, int k) {
  if (k >= NFFT / 2) return 0.0f;
  float pos = (k + 0.5f) * (1.0f / 1024.0f) - 0.5f;
  pos = fminf(fmaxf(pos, 0.0f), 15.0f);
  const int i0 = (int)pos;
  const int i1 = min(i0 + 1, 15);
  const float w = pos - (float)i0;
  return sigf[i0] + (sigf[i1] - sigf[i0]) * w;
}

__device__ __forceinline__ float2 spec_one(float2 Zn, float2 Znm, int n,
                                           const float* __restrict__ sigf) {
  const bool lower = (n <= NFFT / 2);
  const float2 zk = lower ? Zn  : Znm;
  const float2 zm = lower ? Znm : Zn;
  const int k = lower ? n : (NFFT - n);
  const float2 D = make_float2(0.5f * (zk.x + zm.x),  0.5f * (zk.y - zm.y));
  const float2 I = make_float2(0.5f * (zk.y + zm.y), -0.5f * (zk.x - zm.x));
  float2 spec = cmul(D, I);
  const float sc = fenv_of(sigf, k) * SCALE;
  spec.x *= sc; spec.y *= sc;
  return lower ? make_float2(spec.x, -spec.y) : spec;   // conj(Y)
}

// ---------------- kernel 3a: FALLBACK cluster-8 mega kernel ------------------
__global__ void __launch_bounds__(TPB1) __cluster_dims__(8, 1, 1)
k_tail8(const float* __restrict__ filt, float* __restrict__ outr) {
  extern __shared__ float2 dyn[];
  float2* F = dyn;
  float2* G = dyn + SMSZ8;
  __shared__ float sigf[16];
  cg::cluster_group cl = cg::this_cluster();
  const int bt = blockIdx.y;
  const int r  = blockIdx.x;
  const int j  = threadIdx.x;

  if (j < 16) sigf[j] = 1.0f / (1.0f + __expf(-filt[bt * 16 + j]));

  {
    const float2* __restrict__ src = g_bufA + bt * NFFT + r * 4096;
    float2 v[8];
#pragma unroll
    for (int rr = 0; rr < 8; rr++) v[rr] = src[j + rr * TPB1];
    fft8(v);
#pragma unroll
    for (int rr = 0; rr < 8; rr++) F[PADI(j * 8 + rr)] = v[rr];
    __syncthreads();
    smem_stage(F, v, j, 8, TPB1);
    smem_stage(F, v, j, 64, TPB1);
#pragma unroll
    for (int rr = 0; rr < 8; rr++) v[rr] = F[PADI(j + rr * TPB1)];
    twiddle_ramp(v, -(TWO_PI / 4096.0f) * (float)j);
    fft8(v);
    float s, c;
    __sincosf(-(TWO_PI / 32768.0f) * (float)(r * j), &s, &c);
    float2 wb = make_float2(c, s);
    __sincosf(-(TWO_PI / 64.0f) * (float)r, &s, &c);
    const float2 st = make_float2(c, s);
#pragma unroll
    for (int rr = 0; rr < 8; rr++) {
      F[PADI(j + rr * TPB1)] = cmul(v[rr], wb);
      if (rr < 7) wb = cmul(wb, st);
    }
  }
  cl.sync();

  {
    const int a  = r * TPB1 + j;
    const int am = (a == 0) ? 0 : (4096 - a);
    float2 ca[8], cb[8];
    {
      const int pa = PADI(a), pm = PADI(am);
#pragma unroll
      for (int b = 0; b < 8; b++) {
        const float2* Fb = cl.map_shared_rank(F, b);
        ca[b] = Fb[pa];
        cb[b] = Fb[pm];
      }
    }
    fft8(ca);
    if (am != a) fft8(cb); else {
#pragma unroll
      for (int b = 0; b < 8; b++) cb[b] = ca[b];
    }
    float2 v[8];
#pragma unroll
    for (int b = 0; b < 8; b++) {
      const int n  = b * 4096 + a;
      const int rm = (a == 0) ? ((8 - b) & 7) : (7 - b);
      v[b] = spec_one(ca[b], cb[rm], n, sigf);
    }
    fft8(v);
    const int pfull = PADI(a);
    float s, c; __sincosf(-(TWO_PI / 32768.0f) * (float)a, &s, &c);
    const float2 st = make_float2(c, s);
    float2 w = st;
    { float2* dst0 = cl.map_shared_rank(G, 0); dst0[pfull] = v[0]; }
#pragma unroll
    for (int k2 = 1; k2 < 8; k2++) {
      float2* dstk = cl.map_shared_rank(G, k2);
      dstk[pfull] = cmul(v[k2], w);
      if (k2 < 7) w = cmul(w, st);
    }
  }
  cl.sync();

  {
    float2 v[8];
#pragma unroll
    for (int rr = 0; rr < 8; rr++) v[rr] = G[PADI(j + rr * TPB1)];
    __syncthreads();
    fft8(v);
#pragma unroll
    for (int rr = 0; rr < 8; rr++) G[PADI(j * 8 + rr)] = v[rr];
    __syncthreads();
    smem_stage(G, v, j, 8, TPB1);
    smem_stage(G, v, j, 64, TPB1);
#pragma unroll
    for (int rr = 0; rr < 8; rr++) v[rr] = G[PADI(j + rr * TPB1)];
    twiddle_ramp(v, -(TWO_PI / 4096.0f) * (float)j);
    fft8(v);
    float* __restrict__ out = outr + bt * NFFT;
#pragma unroll
    for (int rr = 0; rr < 8; rr++) out[r + 8 * (j + rr * TPB1)] = v[rr].x;
  }
}

// ---------------- kernel 3b: cluster-16 mega kernel (spill-free phase 1) -----
__global__ void __launch_bounds__(TPB2)
k_tail16(const float* __restrict__ filt, float* __restrict__ outr) {
  extern __shared__ float2 dyn[];
  float2* F  = dyn;                      // SMSZ16
  float2* G  = dyn + SMSZ16;             // SMSZ16
  float2* CB = dyn + 2 * SMSZ16;         // CBSZ: mirror Z exchange [k2][t]
  __shared__ float sigf[16];
  cg::cluster_group cl = cg::this_cluster();
  const int bt = blockIdx.y;
  const int cc = blockIdx.x;           // cluster rank = chunk
  const int j  = threadIdx.x;          // 0..255

  if (j < 16) sigf[j] = 1.0f / (1.0f + __expf(-filt[bt * 16 + j]));

  // ---- phase 0: 2048-pt forward FFT of chunk cc into own F, chunk-twiddled --
  {
    const float2* __restrict__ src = g_bufA + bt * NFFT + cc * 2048;
    float2 v[8];
#pragma unroll
    for (int rr = 0; rr < 8; rr++) v[rr] = src[j + rr * TPB2];
    fft8(v);
#pragma unroll
    for (int rr = 0; rr < 8; rr++) F[PADI(j * 8 + rr)] = v[rr];
    __syncthreads();
    smem_stage(F, v, j, 8, TPB2);
    smem_stage(F, v, j, 64, TPB2);

    float2 A[4], B[4];
#pragma unroll
    for (int q = 0; q < 4; q++) A[q] = F[PADI(q * 512 + j)];
#pragma unroll
    for (int q = 0; q < 4; q++) B[q] = F[PADI(q * 512 + j + 256)];
    __syncthreads();
    twiddle_ramp4(A, -(TWO_PI / 2048.0f) * (float)j);
    twiddle_ramp4(B, -(TWO_PI / 2048.0f) * (float)(j + 256));
    fft4(A); fft4(B);
    float s, c;
    __sincosf(-(TWO_PI / 32768.0f) * (float)(cc * j), &s, &c);
    float2 wb = make_float2(c, s);
    __sincosf(-(TWO_PI / 128.0f) * (float)cc, &s, &c);
    const float2 st = make_float2(c, s);
    F[PADI(j)]        = cmul(A[0], wb); wb = cmul(wb, st);
    F[PADI(j + 256)]  = cmul(B[0], wb); wb = cmul(wb, st);
    F[PADI(j + 512)]  = cmul(A[1], wb); wb = cmul(wb, st);
    F[PADI(j + 768)]  = cmul(B[1], wb); wb = cmul(wb, st);
    F[PADI(j + 1024)] = cmul(A[2], wb); wb = cmul(wb, st);
    F[PADI(j + 1280)] = cmul(B[2], wb); wb = cmul(wb, st);
    F[PADI(j + 1536)] = cmul(A[3], wb); wb = cmul(wb, st);
    F[PADI(j + 1792)] = cmul(B[3], wb);
  }
  cl.sync();

  // ---- phase 1: spill-free split --------------------------------------------
  {
    const int t      = j & 127;
    const bool owner = (j < 128);
    const int a_own  = cc * 128 + t;
    const int col    = owner ? a_own : ((a_own == 0) ? 0 : (2048 - a_own));

    float2 z[16];
    {
      const int pc = PADI(col);
#pragma unroll
      for (int b = 0; b < 16; b++) {
        const float2* Fb = cl.map_shared_rank(F, b);
        z[b] = Fb[pc];
      }
    }
    fft16(z);                              // z[k2] = Z[k2*2048 + col]

    if (!owner) {
#pragma unroll
      for (int k2 = 0; k2 < 16; k2++) CB[k2 * 128 + t] = z[k2];
    }
    __syncthreads();

    if (owner) {
#pragma unroll
      for (int k2 = 0; k2 < 16; k2++) {
        const int n  = k2 * 2048 + a_own;
        const int rm = (a_own == 0) ? ((16 - k2) & 15) : (15 - k2);
        z[k2] = spec_one(z[k2], CB[rm * 128 + t], n, sigf);
      }
      fft16(z);

      const int pfull = PADI(a_own);
      float s, c; __sincosf(-(TWO_PI / 32768.0f) * (float)a_own, &s, &c);
      const float2 st = make_float2(c, s);
      float2 w = st;
      { float2* dst0 = cl.map_shared_rank(G, 0); dst0[pfull] = z[0]; }
#pragma unroll
      for (int k2 = 1; k2 < 16; k2++) {
        float2* dstk = cl.map_shared_rank(G, k2);
        dstk[pfull] = cmul(z[k2], w);
        if (k2 < 15) w = cmul(w, st);
      }
    }
  }
  cl.sync();

  // ---- phase 2: 2048-pt inverse FFT of row cc (own G), real output ----------
  {
    float2 v[8];
#pragma unroll
    for (int rr = 0; rr < 8; rr++) v[rr] = G[PADI(j + rr * TPB2)];
    __syncthreads();
    fft8(v);
#pragma unroll
    for (int rr = 0; rr < 8; rr++) G[PADI(j * 8 + rr)] = v[rr];
    __syncthreads();
    smem_stage(G, v, j, 8, TPB2);
    smem_stage(G, v, j, 64, TPB2);

    float2 A[4], B[4];
#pragma unroll
    for (int q = 0; q < 4; q++) A[q] = G[PADI(q * 512 + j)];
#pragma unroll
    for (int q = 0; q < 4; q++) B[q] = G[PADI(q * 512 + j + 256)];
    twiddle_ramp4(A, -(TWO_PI / 2048.0f) * (float)j);
    twiddle_ramp4(B, -(TWO_PI / 2048.0f) * (float)(j + 256));
    fft4(A); fft4(B);

    float* __restrict__ out = outr + bt * NFFT;
    out[16 * (j)        + cc] = A[0].x;
    out[16 * (j + 256)  + cc] = B[0].x;
    out[16 * (j + 512)  + cc] = A[1].x;
    out[16 * (j + 768)  + cc] = B[1].x;
    out[16 * (j + 1024) + cc] = A[2].x;
    out[16 * (j + 1280) + cc] = B[2].x;
    out[16 * (j + 1536) + cc] = A[3].x;
    out[16 * (j + 1792) + cc] = B[3].x;
  }
}

// -------------------------------- launch --------------------------------------
static inline cudaError_t launch_tail16(const float* filt, float* out, int dyn16) {
  cudaLaunchConfig_t cfg = {};
  cfg.gridDim  = dim3(16, BATCH, 1);
  cfg.blockDim = dim3(TPB2, 1, 1);
  cfg.dynamicSmemBytes = (size_t)dyn16;
  cudaLaunchAttribute at[1];
  at[0].id = cudaLaunchAttributeClusterDimension;
  at[0].val.clusterDim.x = 16; at[0].val.clusterDim.y = 1; at[0].val.clusterDim.z = 1;
  cfg.attrs = at; cfg.numAttrs = 1;
  return cudaLaunchKernelEx(&cfg, k_tail16, filt, out);
}

extern "C" void kernel_launch(void* const* d_in, const int* in_sizes, int n_in,
                              void* d_out, int out_size) {
  const float *impulse = nullptr, *dsel = nullptr, *damping = nullptr,
              *filt = nullptr, *noise = nullptr;
  for (int i = 0; i < n_in; i++) {
    switch (in_sizes[i]) {
      case 1024:     impulse = (const float*)d_in[i]; break;  // [8,128]
      case 65536:    dsel    = (const float*)d_in[i]; break;  // [8,512,16]
      case 8:        damping = (const float*)d_in[i]; break;  // [8,1]
      case 128:      filt    = (const float*)d_in[i]; break;  // [8,16]
      case 262144:   noise   = (const float*)d_in[i]; break;  // [8,1,32768]
      default: break;                                         // delays: unused
    }
  }
  float* out = (float*)d_out;
  (void)out_size;

  const int dyn8  = 2 * SMSZ8 * (int)sizeof(float2);                 // 73728
  const int dyn16 = (2 * SMSZ16 + CBSZ) * (int)sizeof(float2);       // 53248

  static int mode = -1;   // 1 = cluster16, 0 = cluster8 fallback
  if (mode < 0) {
    cudaFuncSetAttribute(k_tail8, cudaFuncAttributeMaxDynamicSharedMemorySize, dyn8);
    cudaFuncSetAttribute(k_tail16, cudaFuncAttributeMaxDynamicSharedMemorySize, dyn16);
    cudaFuncSetAttribute(k_tail16, cudaFuncAttributeNonPortableClusterSizeAllowed, 1);

    k_softmax<<<dim3(8, 4), 512>>>(dsel);
    k_build<<<512, 1024>>>(impulse, damping, noise, 15, 4, 2048);
    cudaError_t e = launch_tail16(filt, out, dyn16);
    if (e == cudaSuccess) {
      mode = 1;
    } else {
      cudaGetLastError();
      mode = 0;
      k_build<<<512, 1024>>>(impulse, damping, noise, 7, 3, 4096);
      k_tail8<<<dim3(8, BATCH), TPB1, dyn8>>>(filt, out);
    }
    return;
  }

  k_softmax<<<dim3(8, 4), 512>>>(dsel);
  if (mode == 1) {
    k_build<<<512, 1024>>>(impulse, damping, noise, 15, 4, 2048);
    launch_tail16(filt, out, dyn16);
  } else {
    k_build<<<512, 1024>>>(impulse, damping, noise, 7, 3, 4096);
    k_tail8<<<dim3(8, BATCH), TPB1, dyn8>>>(filt, out);
  }
}

// round 16
// speedup vs baseline: 1.1493x; 1.1493x over previous
#include <cuda_runtime.h>
#include <cooperative_groups.h>
#include <math.h>

namespace cg = cooperative_groups;

#define NFFT   32768
#define BATCH  8
#define TPB1   512       // threads per cluster-8 FFT CTA
#define TPB2   256       // threads per cluster-16 FFT CTA

#define TWO_PI 6.283185307179586476925f
#define SCALE  1.6858739404357614e-07f   // 1 / 32768^1.5

// ---------------- scratch (static device globals; no allocation) -------------
__device__ float  g_S[BATCH * 16 * 512];       // RAW exp [b][f][k] (transposed)
__device__ float  g_part[BATCH * 16 * 16];     // partial sums [b][f][slice]
__device__ float2 g_bufA[BATCH * NFFT];

__device__ __forceinline__ float2 cmul(float2 a, float2 b) {
  return make_float2(a.x*b.x - a.y*b.y, a.x*b.y + a.y*b.x);
}

#define PADI(i) ((i) + ((i) >> 3))
#define SMSZ8   (4096 + 512)     // cluster-8 buffers (4096-pt)
#define SMSZ16  (2048 + 256)     // cluster-16 buffers (2048-pt)
#define CBSZ    (16 * 128)       // mirror-exchange buffer [k2][t]

// ---------------- small DFT kernels (registers) -------------------------------
__device__ __forceinline__ void fft8(float2 v[8]) {
  const float S = 0.70710678118654752440f;
  float2 t;
  t = v[1]; v[1] = v[4]; v[4] = t;      // bit-reverse
  t = v[3]; v[3] = v[6]; v[6] = t;
#define BF(a,b)  { t = v[b]; v[b] = make_float2(v[a].x - t.x, v[a].y - t.y); \
                   v[a] = make_float2(v[a].x + t.x, v[a].y + t.y); }
#define BFMI(a,b){ t = make_float2(v[b].y, -v[b].x); \
                   v[b] = make_float2(v[a].x - t.x, v[a].y - t.y); \
                   v[a] = make_float2(v[a].x + t.x, v[a].y + t.y); }
  BF(0,1) BF(2,3) BF(4,5) BF(6,7)
  BF(0,2) BFMI(1,3) BF(4,6) BFMI(5,7)
  BF(0,4)
  { float2 w = make_float2(S, -S);  t = cmul(w, v[5]);
    v[5] = make_float2(v[1].x - t.x, v[1].y - t.y);
    v[1] = make_float2(v[1].x + t.x, v[1].y + t.y); }
  BFMI(2,6)
  { float2 w = make_float2(-S, -S); t = cmul(w, v[7]);
    v[7] = make_float2(v[3].x - t.x, v[3].y - t.y);
    v[3] = make_float2(v[3].x + t.x, v[3].y + t.y); }
#undef BF
#undef BFMI
}

__device__ __forceinline__ void fft4(float2 v[4]) {
  float2 t;
  t = v[1]; v[1] = v[2]; v[2] = t;      // bit-reverse
  t = v[1]; v[1] = make_float2(v[0].x - t.x, v[0].y - t.y);
            v[0] = make_float2(v[0].x + t.x, v[0].y + t.y);
  t = v[3]; v[3] = make_float2(v[2].x - t.x, v[2].y - t.y);
            v[2] = make_float2(v[2].x + t.x, v[2].y + t.y);
  t = v[2]; v[2] = make_float2(v[0].x - t.x, v[0].y - t.y);
            v[0] = make_float2(v[0].x + t.x, v[0].y + t.y);
  t = make_float2(v[3].y, -v[3].x);
            v[3] = make_float2(v[1].x - t.x, v[1].y - t.y);
            v[1] = make_float2(v[1].x + t.x, v[1].y + t.y);
}

__device__ __forceinline__ void fft16(float2 v[16]) {
  float2 E[8], O[8];
#pragma unroll
  for (int i = 0; i < 8; i++) { E[i] = v[2*i]; O[i] = v[2*i+1]; }
  fft8(E); fft8(O);
  const float2 W16[8] = {
    { 1.0f, 0.0f},
    { 0.9238795325112867f, -0.3826834323650898f},
    { 0.7071067811865476f, -0.7071067811865476f},
    { 0.3826834323650898f, -0.9238795325112867f},
    { 0.0f, -1.0f},
    {-0.3826834323650898f, -0.9238795325112867f},
    {-0.7071067811865476f, -0.7071067811865476f},
    {-0.9238795325112867f, -0.3826834323650898f},
  };
#pragma unroll
  for (int k = 0; k < 8; k++) {
    float2 t = cmul(W16[k], O[k]);
    v[k]     = make_float2(E[k].x + t.x, E[k].y + t.y);
    v[k + 8] = make_float2(E[k].x - t.x, E[k].y - t.y);
  }
}

// v[r] *= exp(i*ang*r): one sincos + chained complex muls (MUFU-cheap)
__device__ __forceinline__ void twiddle_ramp(float2 v[8], float ang) {
  float s, c; __sincosf(ang, &s, &c);
  const float2 st = make_float2(c, s);
  float2 w = st;
  v[1] = cmul(v[1], w);
#pragma unroll
  for (int r = 2; r < 8; r++) { w = cmul(w, st); v[r] = cmul(v[r], w); }
}
__device__ __forceinline__ void twiddle_ramp4(float2 v[4], float ang) {
  float s, c; __sincosf(ang, &s, &c);
  const float2 st = make_float2(c, s);
  float2 w = st;
  v[1] = cmul(v[1], w); w = cmul(w, st);
  v[2] = cmul(v[2], w); w = cmul(w, st);
  v[3] = cmul(v[3], w);
}

// radix-8 Stockham smem stage, stride = TPB (total = 8*TPB points)
__device__ __forceinline__ void smem_stage(float2* sm, float2 v[8], int j, int NS, int TPB) {
#pragma unroll
  for (int r = 0; r < 8; r++) v[r] = sm[PADI(j + r * TPB)];
  __syncthreads();
  const int m = j & (NS - 1);
  twiddle_ramp(v, -(TWO_PI / (8.0f * NS)) * (float)m);
  fft8(v);
  const int base = (j / NS) * (NS * 8) + m;
#pragma unroll
  for (int r = 0; r < 8; r++) sm[PADI(base + r * NS)] = v[r];
  __syncthreads();
}

// ---------------- kernel 1: softmax (raw exps + partial sums) ----------------
__global__ void __launch_bounds__(512) k_softmax(const float* __restrict__ ds) {
  const int b    = blockIdx.x;
  const int tid  = threadIdx.x;
  const int w    = tid >> 5, lane = tid & 31;
  const int q    = w & 3;
  const int kgrp = w >> 2;
  const int k    = blockIdx.y * 128 + kgrp * 32 + lane;

  const float4 x = *(const float4*)(ds + (size_t)b * 8192 + (size_t)k * 16 + q * 4);
  float e0 = __expf(x.x), e1 = __expf(x.y), e2 = __expf(x.z), e3 = __expf(x.w);

  float* Sb = g_S + b * 8192;
  Sb[(q * 4 + 0) * 512 + k] = e0;
  Sb[(q * 4 + 1) * 512 + k] = e1;
  Sb[(q * 4 + 2) * 512 + k] = e2;
  Sb[(q * 4 + 3) * 512 + k] = e3;

  float s0 = e0, s1 = e1, s2 = e2, s3 = e3;
#pragma unroll
  for (int o = 16; o > 0; o >>= 1) {
    s0 += __shfl_xor_sync(0xffffffff, s0, o);
    s1 += __shfl_xor_sync(0xffffffff, s1, o);
    s2 += __shfl_xor_sync(0xffffffff, s2, o);
    s3 += __shfl_xor_sync(0xffffffff, s3, o);
  }
  if (lane == 0) {
    const int slice = blockIdx.y * 4 + kgrp;
    g_part[(b * 16 + q * 4 + 0) * 16 + slice] = s0;
    g_part[(b * 16 + q * 4 + 1) * 16 + slice] = s1;
    g_part[(b * 16 + q * 4 + 2) * 16 + slice] = s2;
    g_part[(b * 16 + q * 4 + 3) * 16 + slice] = s3;
  }
}

// ---------------- kernel 2: comb divisor-sum + impulse + pack ----------------
// 8 sub-threads per sample (proven R7/R14 shape) + hoisted isqrt loop bound.
__global__ void __launch_bounds__(512) k_build(const float* __restrict__ impulse,
                                               const float* __restrict__ damping,
                                               const float* __restrict__ noise,
                                               int cmask, int csh, int n1len) {
  __shared__ float Sf[4096];
  __shared__ float partsm[128];
  __shared__ float binv_sm[8];
  __shared__ float rcp_s[184];
  const int tid = threadIdx.x;
  const int n0  = blockIdx.x * 64;
  const int fr  = n0 >> 11;

  if (tid >= 1 && tid < 184) rcp_s[tid] = 1.0f / (float)tid;
  if (tid < 128) {
    const int b = tid >> 4, sl = tid & 15;
    partsm[tid] = g_part[(b * 16 + fr) * 16 + sl];
  }
#pragma unroll
  for (int i = 0; i < 8; i++) {
    const int idx = tid + i * 512;
    Sf[idx] = g_S[(idx >> 9) * 8192 + fr * 512 + (idx & 511)];
  }
  __syncthreads();
  if (tid < 8) {
    float s = 0.0f;
#pragma unroll
    for (int sl = 0; sl < 16; sl++) s += partsm[tid * 16 + sl];
    binv_sm[tid] = 1.0f / s;
  }
  __syncthreads();

  const int n   = n0 + (tid >> 3);
  const int sub = tid & 7;

  float dsum[BATCH];
#pragma unroll
  for (int b = 0; b < BATCH; b++) dsum[b] = 0.0f;

  {
    // hoisted integer sqrt bound (exact for n < 2^15)
    int limit = (int)sqrtf((float)n);
    if ((limit + 1) * (limit + 1) <= n) limit++;
    if (limit * limit > n) limit--;

    const float nf = (float)n + 0.5f;
    for (int j = sub + 1; j <= limit; j += 8) {
      const int q = (int)(nf * rcp_s[j]);
      if (q * j == n) {
#pragma unroll
        for (int b = 0; b < BATCH; b++) dsum[b] += Sf[b * 512 + (j - 1)];
        if (q != j && q <= 512) {
#pragma unroll
          for (int b = 0; b < BATCH; b++) dsum[b] += Sf[b * 512 + (q - 1)];
        }
      }
    }
  }

  // butterfly combine over the 8 sub-threads
#pragma unroll
  for (int m = 1; m < 8; m <<= 1) {
#pragma unroll
    for (int b = 0; b < BATCH; b++)
      dsum[b] += __shfl_xor_sync(0xffffffff, dsum[b], m);
  }

  // lane 'sub' writes batch b = sub
  {
    const int b = sub;
    float pos = (n + 0.5f) * (1.0f / 256.0f) - 0.5f;
    pos = fminf(fmaxf(pos, 0.0f), 127.0f);
    const int i0 = (int)pos;
    const int i1 = min(i0 + 1, 127);
    const float wgt = pos - (float)i0;
    float a0 = impulse[b * 128 + i0]; a0 *= a0;
    float a1 = impulse[b * 128 + i1]; a1 *= a1;
    const float impv = (a0 * (1.0f - wgt) + a1 * wgt) * noise[b * NFFT + n];
    const float dmp  = 0.9999f / (1.0f + expf(-damping[b]));
    const float dval = (n == 0) ? 1.0f : dsum[b] * binv_sm[b];
    const int pidx = (n & cmask) * n1len + (n >> csh);
    g_bufA[b * NFFT + pidx] = make_float2(dmp * dval, impv);
  }
}

// ---------------- spectrum helpers -------------------------------------------
__device__ __forceinline__ float fenv_of(const float* __restrict__ sigf, int k) {
  if (k >= NFFT / 2) return 0.0f;
  float pos = (k + 0.5f) * (1.0f / 1024.0f) - 0.5f;
  pos = fminf(fmaxf(pos, 0.0f), 15.0f);
  const int i0 = (int)pos;
  const int i1 = min(i0 + 1, 15);
  const float w = pos - (float)i0;
  return sigf[i0] + (sigf[i1] - sigf[i0]) * w;
}

__device__ __forceinline__ float2 spec_one(float2 Zn, float2 Znm, int n,
                                           const float* __restrict__ sigf) {
  const bool lower = (n <= NFFT / 2);
  const float2 zk = lower ? Zn  : Znm;
  const float2 zm = lower ? Znm : Zn;
  const int k = lower ? n : (NFFT - n);
  const float2 D = make_float2(0.5f * (zk.x + zm.x),  0.5f * (zk.y - zm.y));
  const float2 I = make_float2(0.5f * (zk.y + zm.y), -0.5f * (zk.x - zm.x));
  float2 spec = cmul(D, I);
  const float sc = fenv_of(sigf, k) * SCALE;
  spec.x *= sc; spec.y *= sc;
  return lower ? make_float2(spec.x, -spec.y) : spec;   // conj(Y)
}

// ---------------- kernel 3a: FALLBACK cluster-8 mega kernel ------------------
__global__ void __launch_bounds__(TPB1) __cluster_dims__(8, 1, 1)
k_tail8(const float* __restrict__ filt, float* __restrict__ outr) {
  extern __shared__ float2 dyn[];
  float2* F = dyn;
  float2* G = dyn + SMSZ8;
  __shared__ float sigf[16];
  cg::cluster_group cl = cg::this_cluster();
  const int bt = blockIdx.y;
  const int r  = blockIdx.x;
  const int j  = threadIdx.x;

  if (j < 16) sigf[j] = 1.0f / (1.0f + __expf(-filt[bt * 16 + j]));

  {
    const float2* __restrict__ src = g_bufA + bt * NFFT + r * 4096;
    float2 v[8];
#pragma unroll
    for (int rr = 0; rr < 8; rr++) v[rr] = src[j + rr * TPB1];
    fft8(v);
#pragma unroll
    for (int rr = 0; rr < 8; rr++) F[PADI(j * 8 + rr)] = v[rr];
    __syncthreads();
    smem_stage(F, v, j, 8, TPB1);
    smem_stage(F, v, j, 64, TPB1);
#pragma unroll
    for (int rr = 0; rr < 8; rr++) v[rr] = F[PADI(j + rr * TPB1)];
    twiddle_ramp(v, -(TWO_PI / 4096.0f) * (float)j);
    fft8(v);
    float s, c;
    __sincosf(-(TWO_PI / 32768.0f) * (float)(r * j), &s, &c);
    float2 wb = make_float2(c, s);
    __sincosf(-(TWO_PI / 64.0f) * (float)r, &s, &c);
    const float2 st = make_float2(c, s);
#pragma unroll
    for (int rr = 0; rr < 8; rr++) {
      F[PADI(j + rr * TPB1)] = cmul(v[rr], wb);
      if (rr < 7) wb = cmul(wb, st);
    }
  }
  cl.sync();

  {
    const int a  = r * TPB1 + j;
    const int am = (a == 0) ? 0 : (4096 - a);
    float2 ca[8], cb[8];
    {
      const int pa = PADI(a), pm = PADI(am);
#pragma unroll
      for (int b = 0; b < 8; b++) {
        const float2* Fb = cl.map_shared_rank(F, b);
        ca[b] = Fb[pa];
        cb[b] = Fb[pm];
      }
    }
    fft8(ca);
    if (am != a) fft8(cb); else {
#pragma unroll
      for (int b = 0; b < 8; b++) cb[b] = ca[b];
    }
    float2 v[8];
#pragma unroll
    for (int b = 0; b < 8; b++) {
      const int n  = b * 4096 + a;
      const int rm = (a == 0) ? ((8 - b) & 7) : (7 - b);
      v[b] = spec_one(ca[b], cb[rm], n, sigf);
    }
    fft8(v);
    const int pfull = PADI(a);
    float s, c; __sincosf(-(TWO_PI / 32768.0f) * (float)a, &s, &c);
    const float2 st = make_float2(c, s);
    float2 w = st;
    { float2* dst0 = cl.map_shared_rank(G, 0); dst0[pfull] = v[0]; }
#pragma unroll
    for (int k2 = 1; k2 < 8; k2++) {
      float2* dstk = cl.map_shared_rank(G, k2);
      dstk[pfull] = cmul(v[k2], w);
      if (k2 < 7) w = cmul(w, st);
    }
  }
  cl.sync();

  {
    float2 v[8];
#pragma unroll
    for (int rr = 0; rr < 8; rr++) v[rr] = G[PADI(j + rr * TPB1)];
    __syncthreads();
    fft8(v);
#pragma unroll
    for (int rr = 0; rr < 8; rr++) G[PADI(j * 8 + rr)] = v[rr];
    __syncthreads();
    smem_stage(G, v, j, 8, TPB1);
    smem_stage(G, v, j, 64, TPB1);
#pragma unroll
    for (int rr = 0; rr < 8; rr++) v[rr] = G[PADI(j + rr * TPB1)];
    twiddle_ramp(v, -(TWO_PI / 4096.0f) * (float)j);
    fft8(v);
    float* __restrict__ out = outr + bt * NFFT;
#pragma unroll
    for (int rr = 0; rr < 8; rr++) out[r + 8 * (j + rr * TPB1)] = v[rr].x;
  }
}

// ---------------- kernel 3b: cluster-16 mega kernel (spill-free phase 1) -----
__global__ void __launch_bounds__(TPB2)
k_tail16(const float* __restrict__ filt, float* __restrict__ outr) {
  extern __shared__ float2 dyn[];
  float2* F  = dyn;                      // SMSZ16
  float2* G  = dyn + SMSZ16;             // SMSZ16
  float2* CB = dyn + 2 * SMSZ16;         // CBSZ: mirror Z exchange [k2][t]
  __shared__ float sigf[16];
  cg::cluster_group cl = cg::this_cluster();
  const int bt = blockIdx.y;
  const int cc = blockIdx.x;           // cluster rank = chunk
  const int j  = threadIdx.x;          // 0..255

  if (j < 16) sigf[j] = 1.0f / (1.0f + __expf(-filt[bt * 16 + j]));

  // ---- phase 0: 2048-pt forward FFT of chunk cc into own F, chunk-twiddled --
  {
    const float2* __restrict__ src = g_bufA + bt * NFFT + cc * 2048;
    float2 v[8];
#pragma unroll
    for (int rr = 0; rr < 8; rr++) v[rr] = src[j + rr * TPB2];
    fft8(v);
#pragma unroll
    for (int rr = 0; rr < 8; rr++) F[PADI(j * 8 + rr)] = v[rr];
    __syncthreads();
    smem_stage(F, v, j, 8, TPB2);
    smem_stage(F, v, j, 64, TPB2);

    float2 A[4], B[4];
#pragma unroll
    for (int q = 0; q < 4; q++) A[q] = F[PADI(q * 512 + j)];
#pragma unroll
    for (int q = 0; q < 4; q++) B[q] = F[PADI(q * 512 + j + 256)];
    __syncthreads();
    twiddle_ramp4(A, -(TWO_PI / 2048.0f) * (float)j);
    twiddle_ramp4(B, -(TWO_PI / 2048.0f) * (float)(j + 256));
    fft4(A); fft4(B);
    float s, c;
    __sincosf(-(TWO_PI / 32768.0f) * (float)(cc * j), &s, &c);
    float2 wb = make_float2(c, s);
    __sincosf(-(TWO_PI / 128.0f) * (float)cc, &s, &c);
    const float2 st = make_float2(c, s);
    F[PADI(j)]        = cmul(A[0], wb); wb = cmul(wb, st);
    F[PADI(j + 256)]  = cmul(B[0], wb); wb = cmul(wb, st);
    F[PADI(j + 512)]  = cmul(A[1], wb); wb = cmul(wb, st);
    F[PADI(j + 768)]  = cmul(B[1], wb); wb = cmul(wb, st);
    F[PADI(j + 1024)] = cmul(A[2], wb); wb = cmul(wb, st);
    F[PADI(j + 1280)] = cmul(B[2], wb); wb = cmul(wb, st);
    F[PADI(j + 1536)] = cmul(A[3], wb); wb = cmul(wb, st);
    F[PADI(j + 1792)] = cmul(B[3], wb);
  }
  cl.sync();

  // ---- phase 1: spill-free split --------------------------------------------
  {
    const int t      = j & 127;
    const bool owner = (j < 128);
    const int a_own  = cc * 128 + t;
    const int col    = owner ? a_own : ((a_own == 0) ? 0 : (2048 - a_own));

    float2 z[16];
    {
      const int pc = PADI(col);
#pragma unroll
      for (int b = 0; b < 16; b++) {
        const float2* Fb = cl.map_shared_rank(F, b);
        z[b] = Fb[pc];
      }
    }
    fft16(z);                              // z[k2] = Z[k2*2048 + col]

    if (!owner) {
#pragma unroll
      for (int k2 = 0; k2 < 16; k2++) CB[k2 * 128 + t] = z[k2];
    }
    __syncthreads();

    if (owner) {
#pragma unroll
      for (int k2 = 0; k2 < 16; k2++) {
        const int n  = k2 * 2048 + a_own;
        const int rm = (a_own == 0) ? ((16 - k2) & 15) : (15 - k2);
        z[k2] = spec_one(z[k2], CB[rm * 128 + t], n, sigf);
      }
      fft16(z);

      const int pfull = PADI(a_own);
      float s, c; __sincosf(-(TWO_PI / 32768.0f) * (float)a_own, &s, &c);
      const float2 st = make_float2(c, s);
      float2 w = st;
      { float2* dst0 = cl.map_shared_rank(G, 0); dst0[pfull] = z[0]; }
#pragma unroll
      for (int k2 = 1; k2 < 16; k2++) {
        float2* dstk = cl.map_shared_rank(G, k2);
        dstk[pfull] = cmul(z[k2], w);
        if (k2 < 15) w = cmul(w, st);
      }
    }
  }
  cl.sync();

  // ---- phase 2: 2048-pt inverse FFT of row cc (own G), real output ----------
  {
    float2 v[8];
#pragma unroll
    for (int rr = 0; rr < 8; rr++) v[rr] = G[PADI(j + rr * TPB2)];
    __syncthreads();
    fft8(v);
#pragma unroll
    for (int rr = 0; rr < 8; rr++) G[PADI(j * 8 + rr)] = v[rr];
    __syncthreads();
    smem_stage(G, v, j, 8, TPB2);
    smem_stage(G, v, j, 64, TPB2);

    float2 A[4], B[4];
#pragma unroll
    for (int q = 0; q < 4; q++) A[q] = G[PADI(q * 512 + j)];
#pragma unroll
    for (int q = 0; q < 4; q++) B[q] = G[PADI(q * 512 + j + 256)];
    twiddle_ramp4(A, -(TWO_PI / 2048.0f) * (float)j);
    twiddle_ramp4(B, -(TWO_PI / 2048.0f) * (float)(j + 256));
    fft4(A); fft4(B);

    float* __restrict__ out = outr + bt * NFFT;
    out[16 * (j)        + cc] = A[0].x;
    out[16 * (j + 256)  + cc] = B[0].x;
    out[16 * (j + 512)  + cc] = A[1].x;
    out[16 * (j + 768)  + cc] = B[1].x;
    out[16 * (j + 1024) + cc] = A[2].x;
    out[16 * (j + 1280) + cc] = B[2].x;
    out[16 * (j + 1536) + cc] = A[3].x;
    out[16 * (j + 1792) + cc] = B[3].x;
  }
}

// -------------------------------- launch --------------------------------------
static inline cudaError_t launch_tail16(const float* filt, float* out, int dyn16) {
  cudaLaunchConfig_t cfg = {};
  cfg.gridDim  = dim3(16, BATCH, 1);
  cfg.blockDim = dim3(TPB2, 1, 1);
  cfg.dynamicSmemBytes = (size_t)dyn16;
  cudaLaunchAttribute at[1];
  at[0].id = cudaLaunchAttributeClusterDimension;
  at[0].val.clusterDim.x = 16; at[0].val.clusterDim.y = 1; at[0].val.clusterDim.z = 1;
  cfg.attrs = at; cfg.numAttrs = 1;
  return cudaLaunchKernelEx(&cfg, k_tail16, filt, out);
}

extern "C" void kernel_launch(void* const* d_in, const int* in_sizes, int n_in,
                              void* d_out, int out_size) {
  const float *impulse = nullptr, *dsel = nullptr, *damping = nullptr,
              *filt = nullptr, *noise = nullptr;
  for (int i = 0; i < n_in; i++) {
    switch (in_sizes[i]) {
      case 1024:     impulse = (const float*)d_in[i]; break;  // [8,128]
      case 65536:    dsel    = (const float*)d_in[i]; break;  // [8,512,16]
      case 8:        damping = (const float*)d_in[i]; break;  // [8,1]
      case 128:      filt    = (const float*)d_in[i]; break;  // [8,16]
      case 262144:   noise   = (const float*)d_in[i]; break;  // [8,1,32768]
      default: break;                                         // delays: unused
    }
  }
  float* out = (float*)d_out;
  (void)out_size;

  const int dyn8  = 2 * SMSZ8 * (int)sizeof(float2);                 // 73728
  const int dyn16 = (2 * SMSZ16 + CBSZ) * (int)sizeof(float2);       // 53248

  static int mode = -1;   // 1 = cluster16, 0 = cluster8 fallback
  if (mode < 0) {
    cudaFuncSetAttribute(k_tail8, cudaFuncAttributeMaxDynamicSharedMemorySize, dyn8);
    cudaFuncSetAttribute(k_tail16, cudaFuncAttributeMaxDynamicSharedMemorySize, dyn16);
    cudaFuncSetAttribute(k_tail16, cudaFuncAttributeNonPortableClusterSizeAllowed, 1);

    k_softmax<<<dim3(8, 4), 512>>>(dsel);
    k_build<<<512, 512>>>(impulse, damping, noise, 15, 4, 2048);
    cudaError_t e = launch_tail16(filt, out, dyn16);
    if (e == cudaSuccess) {
      mode = 1;
    } else {
      cudaGetLastError();
      mode = 0;
      k_build<<<512, 512>>>(impulse, damping, noise, 7, 3, 4096);
      k_tail8<<<dim3(8, BATCH), TPB1, dyn8>>>(filt, out);
    }
    return;
  }

  k_softmax<<<dim3(8, 4), 512>>>(dsel);
  if (mode == 1) {
    k_build<<<512, 512>>>(impulse, damping, noise, 15, 4, 2048);
    launch_tail16(filt, out, dyn16);
  } else {
    k_build<<<512, 512>>>(impulse, damping, noise, 7, 3, 4096);
    k_tail8<<<dim3(8, BATCH), TPB1, dyn8>>>(filt, out);
  }
}